// round 1
// baseline (speedup 1.0000x reference)
#include <cuda_runtime.h>
#include <cstdint>
#include <cstddef>

// ---------------------------------------------------------------------------
// Show-Attend-Tell decoder, fp32 baseline.
// B=128 batch, P=196 pixels, ENC=2048, EMB=DEC=ATT=512, V=10000, T=20 (19 steps)
// ---------------------------------------------------------------------------

constexpr int B    = 128;
constexpr int P    = 196;
constexpr int ENC  = 2048;
constexpr int EMB  = 512;
constexpr int DEC  = 512;
constexpr int ATT  = 512;
constexpr int VOC  = 10000;
constexpr int T    = 20;
constexpr int NSTEP = T - 1;           // 19
constexpr int G4   = 4 * DEC;          // 2048 (i,f,g,o)
constexpr int HALLN = ATT + ENC + G4;  // 4608: [dec_att | fbeta_pre | hWhh]
constexpr int XDIM = EMB + ENC;        // 2560
constexpr int KSPLIT = 8;
constexpr int KCHUNK = XDIM / KSPLIT;  // 320

// ----------------------------- device scratch ------------------------------
__device__ float g_mean[B * ENC];
__device__ float g_hc[B * 2 * DEC];
__device__ float g_h[B * DEC];
__device__ float g_c[B * DEC];
__device__ float g_encproj[(size_t)B * P * ATT];   // 51.4 MB
__device__ float g_Wall[DEC * HALLN];              // packed [W_dec_att|W_fbeta|W_hh]
__device__ float g_ball[HALLN];
__device__ float g_Winit[ENC * 2 * DEC];           // packed [W_init_h|W_init_c]
__device__ float g_binit[2 * DEC];
__device__ float g_hall[B * HALLN];
__device__ float g_scores[B * P];
__device__ float g_alpha[B * P];
__device__ float g_x[B * XDIM];                    // [emb_t | gate*context]
__device__ float g_gpart[(size_t)KSPLIT * B * G4]; // split-K partials

// ------------------------------- GEMM ---------------------------------------
// C[M,N] = A[M,K] @ B[K,N] (+ bias), row-major. ldb == N. ldc arbitrary.
// Split-K: blockIdx.z selects K range [z*kChunk, (z+1)*kChunk); C advances by
// z*M*ldc (partials). For a full GEMM use gridDim.z = 1, kChunk = K.
// Requires: M % BM == 0, kChunk % BK == 0, N % 4 == 0.
template <int BM, int BN, int BK, int TM, int TN>
__global__ void gemm_tiled(const float* __restrict__ A,
                           const float* __restrict__ Bm,
                           float* __restrict__ C,
                           int M, int N, int K, int ldc,
                           const float* __restrict__ bias,
                           int kChunk) {
    constexpr int THREADS = (BM / TM) * (BN / TN);
    __shared__ float As[BK][BM];
    __shared__ float Bs[BK][BN];

    const int tid = threadIdx.x;
    const int tx  = tid % (BN / TN);
    const int ty  = tid / (BN / TN);
    const int rowBase = blockIdx.y * BM;
    const int colBase = blockIdx.x * BN;
    const int k0 = blockIdx.z * kChunk;
    C += (size_t)blockIdx.z * M * ldc;

    float acc[TM][TN];
#pragma unroll
    for (int i = 0; i < TM; i++)
#pragma unroll
        for (int j = 0; j < TN; j++) acc[i][j] = 0.f;

    constexpr int APT = BM * BK / 4 / THREADS;   // float4 loads/thread for A
    constexpr int BPT = BN * BK / 4 / THREADS;   // float4 loads/thread for B

    for (int kt = 0; kt < kChunk; kt += BK) {
#pragma unroll
        for (int i = 0; i < APT; i++) {
            int f  = tid + i * THREADS;
            int r  = f / (BK / 4);
            int c4 = f % (BK / 4);
            float4 v = *reinterpret_cast<const float4*>(
                &A[(size_t)(rowBase + r) * K + (k0 + kt + c4 * 4)]);
            As[c4 * 4 + 0][r] = v.x;
            As[c4 * 4 + 1][r] = v.y;
            As[c4 * 4 + 2][r] = v.z;
            As[c4 * 4 + 3][r] = v.w;
        }
#pragma unroll
        for (int i = 0; i < BPT; i++) {
            int f  = tid + i * THREADS;
            int r  = f / (BN / 4);
            int c4 = f % (BN / 4);
            int gc = colBase + c4 * 4;
            float4 v;
            if (gc + 3 < N)
                v = *reinterpret_cast<const float4*>(
                    &Bm[(size_t)(k0 + kt + r) * N + gc]);
            else
                v = make_float4(0.f, 0.f, 0.f, 0.f);
            *reinterpret_cast<float4*>(&Bs[r][c4 * 4]) = v;
        }
        __syncthreads();

#pragma unroll
        for (int k = 0; k < BK; k++) {
            float ra[TM], rb[TN];
#pragma unroll
            for (int i = 0; i < TM; i += 4)
                *reinterpret_cast<float4*>(&ra[i]) =
                    *reinterpret_cast<const float4*>(&As[k][ty * TM + i]);
#pragma unroll
            for (int j = 0; j < TN; j += 4)
                *reinterpret_cast<float4*>(&rb[j]) =
                    *reinterpret_cast<const float4*>(&Bs[k][tx * TN + j]);
#pragma unroll
            for (int i = 0; i < TM; i++)
#pragma unroll
                for (int j = 0; j < TN; j++)
                    acc[i][j] = fmaf(ra[i], rb[j], acc[i][j]);
        }
        __syncthreads();
    }

    const bool hasBias = (bias != nullptr);
#pragma unroll
    for (int i = 0; i < TM; i++) {
        int r = rowBase + ty * TM + i;
#pragma unroll
        for (int j = 0; j < TN; j++) {
            int cN = colBase + tx * TN + j;
            if (cN < N) {
                float v = acc[i][j];
                if (hasBias) v += bias[cN];
                C[(size_t)r * ldc + cN] = v;
            }
        }
    }
}

// --------------------------- packing kernels --------------------------------
__global__ void pack_wall(const float* __restrict__ Wd,
                          const float* __restrict__ Wf,
                          const float* __restrict__ Whh) {
    int idx = blockIdx.x * 256 + threadIdx.x;
    if (idx >= DEC * HALLN) return;
    int r = idx / HALLN, c = idx % HALLN;
    float v;
    if (c < ATT)              v = Wd[r * ATT + c];
    else if (c < ATT + ENC)   v = Wf[r * ENC + (c - ATT)];
    else                      v = Whh[r * G4 + (c - ATT - ENC)];
    g_Wall[idx] = v;
}

__global__ void pack_ball(const float* __restrict__ bd,
                          const float* __restrict__ bf,
                          const float* __restrict__ bhh,
                          const float* __restrict__ bih) {
    int c = blockIdx.x * 256 + threadIdx.x;
    if (c >= HALLN) return;
    float v;
    if (c < ATT)              v = bd[c];
    else if (c < ATT + ENC)   v = bf[c - ATT];
    else                      v = bhh[c - ATT - ENC] + bih[c - ATT - ENC];
    g_ball[c] = v;
}

__global__ void pack_winit(const float* __restrict__ Wh,
                           const float* __restrict__ Wc) {
    int idx = blockIdx.x * 256 + threadIdx.x;
    if (idx >= ENC * 2 * DEC) return;
    int r = idx / (2 * DEC), c = idx % (2 * DEC);
    g_Winit[idx] = (c < DEC) ? Wh[r * DEC + c] : Wc[r * DEC + (c - DEC)];
}

__global__ void pack_binit(const float* __restrict__ bh,
                           const float* __restrict__ bc) {
    int c = blockIdx.x * 256 + threadIdx.x;
    if (c >= 2 * DEC) return;
    g_binit[c] = (c < DEC) ? bh[c] : bc[c - DEC];
}

__global__ void split_hc() {
    int idx = blockIdx.x * 256 + threadIdx.x;  // B*DEC
    int b = idx / DEC, d = idx % DEC;
    g_h[idx] = g_hc[b * 2 * DEC + d];
    g_c[idx] = g_hc[b * 2 * DEC + DEC + d];
}

// -------------------------- per-problem kernels -----------------------------
__global__ void mean_kernel(const float* __restrict__ enc_out) {
    int idx = blockIdx.x * 256 + threadIdx.x;   // B*ENC
    int b = idx / ENC, e = idx % ENC;
    const float* src = enc_out + (size_t)b * P * ENC + e;
    float s = 0.f;
#pragma unroll 4
    for (int p = 0; p < P; p++) s += src[(size_t)p * ENC];
    g_mean[idx] = s * (1.f / 196.f);
}

__global__ void embed_kernel(const float* __restrict__ emb,
                             const int* __restrict__ cap, int t) {
    int b = blockIdx.x, tid = threadIdx.x;     // 128 threads
    int cidx = cap[b * T + t];
    const float4* src = reinterpret_cast<const float4*>(emb + (size_t)cidx * EMB);
    float4* dst = reinterpret_cast<float4*>(g_x + (size_t)b * XDIM);
    dst[tid] = src[tid];
}

// scores[b,p] = sum_a relu(enc_proj[b,p,a] + dec_att[b,a]) * w_att[a] + b_att
__global__ void scores_kernel(const float* __restrict__ w_att,
                              const float* __restrict__ b_att) {
    __shared__ float s_dec[ATT];
    __shared__ float s_w[ATT];
    int b = blockIdx.x, tid = threadIdx.x;
    for (int i = tid; i < ATT; i += 256) {
        s_dec[i] = g_hall[b * HALLN + i];
        s_w[i]   = w_att[i];
    }
    __syncthreads();
    int warp = tid >> 5, lane = tid & 31;
    int p = blockIdx.y * 8 + warp;
    if (p >= P) return;
    const float* ep = &g_encproj[((size_t)(b * P + p)) * ATT];
    float s = 0.f;
#pragma unroll 4
    for (int a = lane; a < ATT; a += 32) {
        float e = ep[a] + s_dec[a];
        s += fmaxf(e, 0.f) * s_w[a];
    }
#pragma unroll
    for (int o = 16; o; o >>= 1) s += __shfl_down_sync(0xffffffffu, s, o);
    if (lane == 0) g_scores[b * P + p] = s + b_att[0];
}

__global__ void softmax_kernel() {
    __shared__ float red[256];
    int b = blockIdx.x, tid = threadIdx.x;
    float v = (tid < P) ? g_scores[b * P + tid] : -1e30f;
    red[tid] = v;
    __syncthreads();
    for (int o = 128; o; o >>= 1) {
        if (tid < o) red[tid] = fmaxf(red[tid], red[tid + o]);
        __syncthreads();
    }
    float m = red[0];
    __syncthreads();
    float e = (tid < P) ? expf(v - m) : 0.f;
    red[tid] = e;
    __syncthreads();
    for (int o = 128; o; o >>= 1) {
        if (tid < o) red[tid] += red[tid + o];
        __syncthreads();
    }
    float inv = 1.f / red[0];
    if (tid < P) g_alpha[b * P + tid] = e * inv;
}

// x[b, EMB+ch] = sigmoid(fbeta_pre[b,ch]) * sum_p alpha[b,p]*enc_out[b,p,ch]
__global__ void context_kernel(const float* __restrict__ enc_out) {
    __shared__ float s_a[P];
    int b = blockIdx.x, tid = threadIdx.x;
    int ch = blockIdx.y * 256 + tid;
    if (tid < P) s_a[tid] = g_alpha[b * P + tid];
    __syncthreads();
    const float* eb = enc_out + (size_t)b * P * ENC + ch;
    float acc = 0.f;
#pragma unroll 4
    for (int p = 0; p < P; p++) acc = fmaf(s_a[p], eb[(size_t)p * ENC], acc);
    float gpre = g_hall[b * HALLN + ATT + ch];
    float gate = 1.f / (1.f + expf(-gpre));
    g_x[(size_t)b * XDIM + EMB + ch] = gate * acc;
}

// Deterministic split-K reduce + LSTM cell, updates g_h/g_c in place.
__global__ void lstm_kernel() {
    int idx = blockIdx.x * 256 + threadIdx.x;  // B*DEC
    if (idx >= B * DEC) return;
    int b = idx / DEC, d = idx % DEC;
    const float* hallg = &g_hall[b * HALLN + ATT + ENC];  // hWhh + b_hh + b_ih
    float gi = hallg[d];
    float gf = hallg[DEC + d];
    float gg = hallg[2 * DEC + d];
    float go = hallg[3 * DEC + d];
#pragma unroll
    for (int s = 0; s < KSPLIT; s++) {
        const float* pp = &g_gpart[((size_t)s * B + b) * G4];
        gi += pp[d];
        gf += pp[DEC + d];
        gg += pp[2 * DEC + d];
        go += pp[3 * DEC + d];
    }
    float c  = g_c[idx];
    float si = 1.f / (1.f + expf(-gi));
    float sf = 1.f / (1.f + expf(-gf));
    float so = 1.f / (1.f + expf(-go));
    float cn = sf * c + si * tanhf(gg);
    float hn = so * tanhf(cn);
    g_c[idx] = cn;
    g_h[idx] = hn;
}

// ------------------------------- launcher -----------------------------------
extern "C" void kernel_launch(void* const* d_in, const int* in_sizes, int n_in,
                              void* d_out, int out_size) {
    const float* enc_out   = (const float*)d_in[0];
    const int*   captions  = (const int*)  d_in[1];
    const float* emb       = (const float*)d_in[2];
    const float* W_init_h  = (const float*)d_in[3];
    const float* b_init_h  = (const float*)d_in[4];
    const float* W_init_c  = (const float*)d_in[5];
    const float* b_init_c  = (const float*)d_in[6];
    const float* W_enc_att = (const float*)d_in[7];
    const float* b_enc_att = (const float*)d_in[8];
    const float* W_dec_att = (const float*)d_in[9];
    const float* b_dec_att = (const float*)d_in[10];
    const float* w_att     = (const float*)d_in[11];
    const float* b_att     = (const float*)d_in[12];
    const float* W_fbeta   = (const float*)d_in[13];
    const float* b_fbeta   = (const float*)d_in[14];
    const float* W_ih      = (const float*)d_in[15];
    const float* b_ih      = (const float*)d_in[16];
    const float* W_hh      = (const float*)d_in[17];
    const float* b_hh      = (const float*)d_in[18];
    const float* W_fc      = (const float*)d_in[19];
    const float* b_fc      = (const float*)d_in[20];
    float* out = (float*)d_out;

    float *p_mean, *p_hc, *p_h, *p_encproj, *p_Wall, *p_ball,
          *p_Winit, *p_binit, *p_hall, *p_x, *p_gpart;
    cudaGetSymbolAddress((void**)&p_mean,    g_mean);
    cudaGetSymbolAddress((void**)&p_hc,      g_hc);
    cudaGetSymbolAddress((void**)&p_h,       g_h);
    cudaGetSymbolAddress((void**)&p_encproj, g_encproj);
    cudaGetSymbolAddress((void**)&p_Wall,    g_Wall);
    cudaGetSymbolAddress((void**)&p_ball,    g_ball);
    cudaGetSymbolAddress((void**)&p_Winit,   g_Winit);
    cudaGetSymbolAddress((void**)&p_binit,   g_binit);
    cudaGetSymbolAddress((void**)&p_hall,    g_hall);
    cudaGetSymbolAddress((void**)&p_x,       g_x);
    cudaGetSymbolAddress((void**)&p_gpart,   g_gpart);

    // ---- one-time precompute ----
    pack_wall <<<(DEC * HALLN + 255) / 256, 256>>>(W_dec_att, W_fbeta, W_hh);
    pack_ball <<<(HALLN + 255) / 256, 256>>>(b_dec_att, b_fbeta, b_hh, b_ih);
    pack_winit<<<(ENC * 2 * DEC + 255) / 256, 256>>>(W_init_h, W_init_c);
    pack_binit<<<(2 * DEC + 255) / 256, 256>>>(b_init_h, b_init_c);
    mean_kernel<<<B * ENC / 256, 256>>>(enc_out);

    // [h0|c0] = mean @ [W_init_h|W_init_c] + [b_init_h|b_init_c]
    gemm_tiled<64, 64, 16, 4, 4><<<dim3(2 * DEC / 64, B / 64, 1), 256>>>(
        p_mean, p_Winit, p_hc, B, 2 * DEC, ENC, 2 * DEC, p_binit, ENC);
    split_hc<<<B * DEC / 256, 256>>>();

    // enc_proj = enc_out @ W_enc_att + b_enc_att   [25088, 512]
    gemm_tiled<128, 128, 16, 8, 8><<<dim3(ATT / 128, B * P / 128, 1), 256>>>(
        enc_out, W_enc_att, p_encproj, B * P, ATT, ENC, ATT, b_enc_att, ENC);

    // ---- decode loop ----
    for (int t = 0; t < NSTEP; t++) {
        // hall = h @ [W_dec_att|W_fbeta|W_hh] + ball    [128, 4608]
        gemm_tiled<64, 64, 16, 4, 4><<<dim3(HALLN / 64, B / 64, 1), 256>>>(
            p_h, p_Wall, p_hall, B, HALLN, DEC, HALLN, p_ball, DEC);

        embed_kernel<<<B, 128>>>(emb, captions, t);
        scores_kernel<<<dim3(B, (P + 7) / 8), 256>>>(w_att, b_att);
        softmax_kernel<<<B, 256>>>();
        context_kernel<<<dim3(B, ENC / 256), 256>>>(enc_out);

        // gates partials = x @ W_ih, split-K over XDIM=2560 into 8 chunks
        gemm_tiled<128, 128, 16, 8, 8><<<dim3(G4 / 128, 1, KSPLIT), 256>>>(
            p_x, W_ih, p_gpart, B, G4, XDIM, G4, nullptr, KCHUNK);

        lstm_kernel<<<B * DEC / 256, 256>>>();

        // out[:, t, :] = h_new @ W_fc + b_fc
        gemm_tiled<128, 128, 16, 8, 8><<<dim3((VOC + 127) / 128, 1, 1), 256>>>(
            p_h, W_fc, out + (size_t)t * VOC, B, VOC, DEC, NSTEP * VOC, b_fc,
            DEC);
    }
}